// round 11
// baseline (speedup 1.0000x reference)
#include <cuda_runtime.h>
#include <cuda_fp16.h>
#include <cstdint>

// ============================================================================
// out_i = || P * U(params) * s_i ||^2, 131072 states of dim 256.
// params batch-invariant -> precompute A = P*U (128x256 complex).
// Gauss/Karatsuba 3M complex GEMM, fp16 mma.sync, fp32 accumulation:
//   w = c+di, s = a+bi:  k1=(a+b)c, k2=a(d-c), k3=b(c+d)
//   Re = k1-k3, Im = k1+k2;  out_m = sum_n Re^2+Im^2
// Planes: p0: Ssum x c, p1: Sr x (d-c), p2: Si x (c+d); Ssum fragments are
// derived from Sr/Si fragments with HADD2 (no third A operand in smem).
//
// R11: R6-quality pipeline on the Gauss math. R6 measured exactly the
//  16cyc/SMSP HMMA floor (111.6us); Gauss floor is 0.75x = ~85us. R10 missed
//  it via MLP-4 A loads, 2 syncs/chunk, reg spills (acc=192), 18 LDSM/ks.
//  Fix: CTA 64x128c (acc=96), B fully resident (192KB, loaded once),
//  MLP-8 A batches, 1 sync/chunk, 10 LDSM per 24 MMAs.
// ============================================================================

#define NLAYERS 3
#define NQ 8

// Wg[op][n][k]: op0 = Ar, op1 = Ai - Ar, op2 = Ar + Ai.  (128 n x 256 k each)
__device__ __half Wg_global[3 * 128 * 256];

// ---------------------------------------------------------------------------
__device__ __forceinline__ uint32_t smem_u32(const void* p) {
    uint32_t a;
    asm("{ .reg .u64 t; cvta.to.shared.u64 t, %1; cvt.u32.u64 %0, t; }"
        : "=r"(a) : "l"(p));
    return a;
}

__device__ __forceinline__ void ldmatrix_x4(uint32_t r[4], uint32_t addr) {
    asm volatile("ldmatrix.sync.aligned.m8n8.x4.shared.b16 {%0,%1,%2,%3}, [%4];"
                 : "=r"(r[0]), "=r"(r[1]), "=r"(r[2]), "=r"(r[3]) : "r"(addr));
}

__device__ __forceinline__ void mma16816(float c[4], const uint32_t a[4],
                                         uint32_t b0, uint32_t b1) {
    asm volatile(
        "mma.sync.aligned.m16n8k16.row.col.f32.f16.f16.f32 "
        "{%0,%1,%2,%3}, {%4,%5,%6,%7}, {%8,%9}, {%0,%1,%2,%3};"
        : "+f"(c[0]), "+f"(c[1]), "+f"(c[2]), "+f"(c[3])
        : "r"(a[0]), "r"(a[1]), "r"(a[2]), "r"(a[3]), "r"(b0), "r"(b1));
}

__device__ __forceinline__ uint32_t hadd2u(uint32_t x, uint32_t y) {
    uint32_t z;
    asm("add.f16x2 %0, %1, %2;" : "=r"(z) : "r"(x), "r"(y));
    return z;
}

__device__ __forceinline__ void cp_async16(uint32_t dst, const void* src) {
    asm volatile("cp.async.cg.shared.global [%0], [%1], 16;"
                 :: "r"(dst), "l"(src) : "memory");
}
#define CP_COMMIT() asm volatile("cp.async.commit_group;" ::: "memory")
#define CP_WAIT0()  asm volatile("cp.async.wait_group 0;" ::: "memory")

// ---------------------------------------------------------------------------
// Setup: block k simulates basis state |k>; writes the 3 Karatsuba weights.
// ---------------------------------------------------------------------------
__global__ void build_weights_kernel(const float* __restrict__ params) {
    __shared__ float2 st[256];
    __shared__ float g[NLAYERS * NQ][8];
    int k = blockIdx.x;
    int t = threadIdx.x;

    if (t < NLAYERS * NQ) {
        const float* pr = params + t * 3;
        float hx = 0.5f * pr[0], hy = 0.5f * pr[1], hz = 0.5f * pr[2];
        float cx = cosf(hx), sx = sinf(hx);
        float cy = cosf(hy), sy = sinf(hy);
        float cz = cosf(hz), sz = sinf(hz);
        float m00r =  cy * cx, m00i =  sy * sx;
        float m01r = -sy * cx, m01i = -cy * sx;
        float m10r =  sy * cx, m10i = -cy * sx;
        float m11r =  cy * cx, m11i = -sy * sx;
        g[t][0] = cz * m00r + sz * m00i;  g[t][1] = cz * m00i - sz * m00r;
        g[t][2] = cz * m01r + sz * m01i;  g[t][3] = cz * m01i - sz * m01r;
        g[t][4] = cz * m10r - sz * m10i;  g[t][5] = cz * m10i + sz * m10r;
        g[t][6] = cz * m11r - sz * m11i;  g[t][7] = cz * m11i + sz * m11r;
    }
    st[t] = make_float2(t == k ? 1.0f : 0.0f, 0.0f);
    __syncthreads();

    for (int l = 0; l < NLAYERS; l++) {
        for (int q = 0; q < NQ; q++) {
            const float* u = g[l * NQ + q];
            float u00r = u[0], u00i = u[1], u01r = u[2], u01i = u[3];
            float u10r = u[4], u10i = u[5], u11r = u[6], u11i = u[7];
            int p = 7 - q;  // qubit 0 = MSB of flat index
            if (t < 128) {
                int lo = t & ((1 << p) - 1);
                int i0 = ((t >> p) << (p + 1)) | lo;
                int i1 = i0 | (1 << p);
                float2 a0 = st[i0], a1 = st[i1];
                float2 n0, n1;
                n0.x = u00r*a0.x - u00i*a0.y + u01r*a1.x - u01i*a1.y;
                n0.y = u00r*a0.y + u00i*a0.x + u01r*a1.y + u01i*a1.x;
                n1.x = u10r*a0.x - u10i*a0.y + u11r*a1.x - u11i*a1.y;
                n1.y = u10r*a0.y + u10i*a0.x + u11r*a1.y + u11i*a1.x;
                st[i0] = n0;
                st[i1] = n1;
            }
            __syncthreads();
        }
        for (int q = 0; q < NQ; q++) {
            int pc = 7 - q;
            int pt = 7 - ((q + 1) & 7);
            if (((t >> pc) & 1) == 1 && ((t >> pt) & 1) == 0) {
                int j = t | (1 << pt);
                float2 tmp = st[t];
                st[t] = st[j];
                st[j] = tmp;
            }
            __syncthreads();
        }
    }
    if (t < 128) {
        float re = st[t].x, im = st[t].y;
        Wg_global[0 * 32768 + t * 256 + k] = __float2half_rn(re);
        Wg_global[1 * 32768 + t * 256 + k] = __float2half_rn(im - re);
        Wg_global[2 * 32768 + t * 256 + k] = __float2half_rn(re + im);
    }
}

// ---------------------------------------------------------------------------
// GEMM: grid = 2048 m-tiles. CTA = 64 rows x 128 complex cols, 256 threads =
// 8 warps, warp grid 2(M) x 4(N), warp tile 32 x 32c x 3 planes.
// K = 256 in 4 chunks of 64.
// SMEM: A fp16 [stage(2) x op(2) x 8KB] = 32KB at 0 (op0=Sr, op1=Si);
//       B fp16 resident [chunk(4) x op(3) x 16KB] = 192KB at 32KB.
//       red[64] aliases A (offset 0) in the epilogue.
// ---------------------------------------------------------------------------
static constexpr uint32_t OFF_B    = 32 * 1024;
static constexpr uint32_t DYN_SMEM = 32 * 1024 + 192 * 1024 + 1024;

__global__ void __launch_bounds__(256, 1)
qmm_kernel(const float* __restrict__ sre, const float* __restrict__ sim,
           float* __restrict__ out) {
    extern __shared__ char smem_raw[];
    uint32_t base  = smem_u32(smem_raw);
    uint32_t abase = (base + 1023u) & ~1023u;
    char* a = smem_raw + (abase - base);
    float* red = (float*)a;   // aliases A region (dead by epilogue)

    const int tid  = threadIdx.x;
    const int wid  = tid >> 5;
    const int lane = tid & 31;
    const int wm   = wid >> 2;  // 0..1 : rows wm*32..+31
    const int wn   = wid & 3;   // 0..3 : complex cols wn*32..+31

    // ldmatrix per-lane geometry
    const int r  = lane & 7;
    const int q  = lane >> 3;
    const uint32_t xorv = (uint32_t)r << 4;
    const uint32_t ch16 = (uint32_t)(q >> 1) << 4;
    const int rl = ((q & 1) << 3) + r;

    uint32_t aRow[2], bRow[2];
    #pragma unroll
    for (int mf = 0; mf < 2; mf++)
        aRow[mf] = abase + (uint32_t)(wm * 32 + mf * 16 + rl) * 128;
    #pragma unroll
    for (int nb = 0; nb < 2; nb++)
        bRow[nb] = abase + OFF_B + (uint32_t)(wn * 32 + nb * 16 + rl) * 128;

    const long tileBase = (long)blockIdx.x * 64;

    // acc[plane][mf][nf][i] : 96 regs
    float acc[3][2][4][4];
    #pragma unroll
    for (int p = 0; p < 3; p++)
        #pragma unroll
        for (int mf = 0; mf < 2; mf++)
            #pragma unroll
            for (int nf = 0; nf < 4; nf++)
                #pragma unroll
                for (int i = 0; i < 4; i++) acc[p][mf][nf][i] = 0.0f;

    // ---- B resident load: 12288 x 16B segments, 256 thr -> 48 each ----
    #pragma unroll
    for (int it = 0; it < 48; it++) {
        int i = tid + it * 256;
        int c  = i / 3072;
        int rm = i % 3072;
        int op = rm >> 10;
        int j  = rm & 1023;
        int n = j >> 3, seg = j & 7;
        uint32_t dst = abase + OFF_B + (uint32_t)(c * 3 + op) * 16384u +
                       (uint32_t)n * 128 +
                       (((uint32_t)seg * 16) ^ (((uint32_t)n & 7) << 4));
        cp_async16(dst, Wg_global + op * 32768 + n * 256 + c * 64 + seg * 8);
    }
    CP_COMMIT();

    // A: per chunk 64 rows x 16 float4 per source; 256 thr -> 4 + 4 (MLP 8)
    float4 av[8];

    auto ldgA = [&](int c) {
        int kb = c * 64;
        #pragma unroll
        for (int it = 0; it < 4; it++) {
            int i = tid + it * 256;
            int row = i >> 4, f4 = i & 15;
            av[it]     = *(const float4*)(sre + (tileBase + row) * 256 + kb + f4 * 4);
            av[4 + it] = *(const float4*)(sim + (tileBase + row) * 256 + kb + f4 * 4);
        }
    };
    auto stsA = [&](int c) {
        uint32_t stg = (uint32_t)(c & 1) * 16384u;
        #pragma unroll
        for (int it = 0; it < 4; it++) {
            int i = tid + it * 256;
            int row = i >> 4, f4 = i & 15;
            uint32_t byte = (uint32_t)row * 128 +
                            (((uint32_t)f4 * 8) ^ (((uint32_t)row & 7) << 4));
            __half2 r0 = __floats2half2_rn(av[it].x, av[it].y);
            __half2 r1 = __floats2half2_rn(av[it].z, av[it].w);
            __half2 i0 = __floats2half2_rn(av[4 + it].x, av[4 + it].y);
            __half2 i1 = __floats2half2_rn(av[4 + it].z, av[4 + it].w);
            uint2 v;
            v.x = *(const uint32_t*)&r0; v.y = *(const uint32_t*)&r1;
            *(uint2*)(a + stg + byte) = v;              // op0 = Sr
            v.x = *(const uint32_t*)&i0; v.y = *(const uint32_t*)&i1;
            *(uint2*)(a + stg + 8192 + byte) = v;       // op1 = Si
        }
    };
    auto compute_ks = [&](int c, int ks) {
        uint32_t cx  = (((uint32_t)ks * 32) | ch16) ^ xorv;
        uint32_t stg = (uint32_t)(c & 1) * 16384u;
        uint32_t fr[2][4], fi[2][4], fs[2][4];
        #pragma unroll
        for (int mf = 0; mf < 2; mf++) {
            ldmatrix_x4(fr[mf], aRow[mf] + stg + cx);            // Sr
            ldmatrix_x4(fi[mf], aRow[mf] + stg + 8192u + cx);    // Si
            #pragma unroll
            for (int j = 0; j < 4; j++)
                fs[mf][j] = hadd2u(fr[mf][j], fi[mf][j]);        // Ssum
        }
        uint32_t bf[3][2][4];
        #pragma unroll
        for (int op = 0; op < 3; op++)
            #pragma unroll
            for (int nb = 0; nb < 2; nb++)
                ldmatrix_x4(bf[op][nb],
                            bRow[nb] + (uint32_t)(c * 3 + op) * 16384u + cx);
        #pragma unroll
        for (int mf = 0; mf < 2; mf++)
            #pragma unroll
            for (int nf = 0; nf < 4; nf++) {
                int nb = nf >> 1, sub = nf & 1;
                mma16816(acc[0][mf][nf], fs[mf], bf[0][nb][sub], bf[0][nb][sub + 2]);
                mma16816(acc[1][mf][nf], fr[mf], bf[1][nb][sub], bf[1][nb][sub + 2]);
                mma16816(acc[2][mf][nf], fi[mf], bf[2][nb][sub], bf[2][nb][sub + 2]);
            }
    };

    // ---- prologue: A(0) into stage 0; wait B ----
    ldgA(0);
    stsA(0);
    CP_WAIT0();
    __syncthreads();

    // ---- mainloop: 4 chunks of K=64, one sync per chunk ----
    for (int c = 0; c < 4; c++) {
        if (c < 3) ldgA(c + 1);
        compute_ks(c, 0);
        compute_ks(c, 1);
        if (c < 3) stsA(c + 1);
        compute_ks(c, 2);
        compute_ks(c, 3);
        __syncthreads();
    }

    // ---- epilogue: Re = k1-k3, Im = k1+k2; out[m] = sum Re^2+Im^2 ----
    if (tid < 64) red[tid] = 0.0f;
    __syncthreads();

    #pragma unroll
    for (int mf = 0; mf < 2; mf++) {
        float s_lo = 0.0f, s_hi = 0.0f;
        #pragma unroll
        for (int nf = 0; nf < 4; nf++) {
            #pragma unroll
            for (int i = 0; i < 4; i++) {
                float k1 = acc[0][mf][nf][i];
                float k2 = acc[1][mf][nf][i];
                float k3 = acc[2][mf][nf][i];
                float re = k1 - k3;
                float im = k1 + k2;
                float v = fmaf(re, re, im * im);
                if (i < 2) s_lo += v; else s_hi += v;
            }
        }
        s_lo += __shfl_xor_sync(0xFFFFFFFF, s_lo, 1);
        s_lo += __shfl_xor_sync(0xFFFFFFFF, s_lo, 2);
        s_hi += __shfl_xor_sync(0xFFFFFFFF, s_hi, 1);
        s_hi += __shfl_xor_sync(0xFFFFFFFF, s_hi, 2);
        if ((lane & 3) == 0) {
            int row = wm * 32 + mf * 16 + (lane >> 2);
            atomicAdd(red + row, s_lo);
            atomicAdd(red + row + 8, s_hi);
        }
    }
    __syncthreads();
    if (tid < 64) out[tileBase + tid] = red[tid];
}

// ---------------------------------------------------------------------------
extern "C" void kernel_launch(void* const* d_in, const int* in_sizes, int n_in,
                              void* d_out, int out_size) {
    const float* params = (const float*)d_in[0];
    const float* sre    = (const float*)d_in[1];
    const float* sim    = (const float*)d_in[2];
    float* out = (float*)d_out;

    cudaFuncSetAttribute(qmm_kernel, cudaFuncAttributeMaxDynamicSharedMemorySize,
                         DYN_SMEM);

    build_weights_kernel<<<256, 256>>>(params);
    qmm_kernel<<<2048, 256, DYN_SMEM>>>(sre, sim, out);
}

// round 12
// speedup vs baseline: 1.1426x; 1.1426x over previous
#include <cuda_runtime.h>
#include <cuda_fp16.h>
#include <cstdint>

// ============================================================================
// out_i = || P * U(params) * s_i ||^2, 131072 states of dim 256.
// params batch-invariant -> precompute A = P*U (128x256 complex).
// Gauss/Karatsuba 3M complex GEMM, fp16 mma.sync, fp32 accumulation:
//   w = c+di, s = a+bi:  k1=(a+b)c, k2=a(d-c), k3=b(c+d)
//   Re = k1-k3, Im = k1+k2;  out_m = sum_n Re^2+Im^2
// Planes: p0: Ssum x c, p1: Sr x (d-c), p2: Si x (c+d); Ssum fragments
// derived from Sr/Si fragments via HADD2.
//
// R12: all measured defects removed at once.
//  - R11's killer (resident-B prologue serialization) -> 3-stage cp.async
//    ring issued 2 chunks ahead (R10's overlap pattern).
//  - R10's killers (acc=192 + spills, MLP-4 A loads, 2 syncs/chunk) ->
//    warp tile 64x16c (acc=96, ~215 regs total), MLP-8 A batches, single
//    sync per chunk.
//  MMA floor for Gauss = 0.75 x R6's measured 111.6us = ~85us.
// ============================================================================

#define NLAYERS 3
#define NQ 8

// Wg[op][n][k]: op0 = Ar, op1 = Ai - Ar, op2 = Ar + Ai.  (128 n x 256 k each)
__device__ __half Wg_global[3 * 128 * 256];

// ---------------------------------------------------------------------------
__device__ __forceinline__ uint32_t smem_u32(const void* p) {
    uint32_t a;
    asm("{ .reg .u64 t; cvta.to.shared.u64 t, %1; cvt.u32.u64 %0, t; }"
        : "=r"(a) : "l"(p));
    return a;
}

__device__ __forceinline__ void ldmatrix_x4(uint32_t r[4], uint32_t addr) {
    asm volatile("ldmatrix.sync.aligned.m8n8.x4.shared.b16 {%0,%1,%2,%3}, [%4];"
                 : "=r"(r[0]), "=r"(r[1]), "=r"(r[2]), "=r"(r[3]) : "r"(addr));
}

__device__ __forceinline__ void mma16816(float c[4], const uint32_t a[4],
                                         uint32_t b0, uint32_t b1) {
    asm volatile(
        "mma.sync.aligned.m16n8k16.row.col.f32.f16.f16.f32 "
        "{%0,%1,%2,%3}, {%4,%5,%6,%7}, {%8,%9}, {%0,%1,%2,%3};"
        : "+f"(c[0]), "+f"(c[1]), "+f"(c[2]), "+f"(c[3])
        : "r"(a[0]), "r"(a[1]), "r"(a[2]), "r"(a[3]), "r"(b0), "r"(b1));
}

__device__ __forceinline__ uint32_t hadd2u(uint32_t x, uint32_t y) {
    uint32_t z;
    asm("add.f16x2 %0, %1, %2;" : "=r"(z) : "r"(x), "r"(y));
    return z;
}

__device__ __forceinline__ void cp_async16(uint32_t dst, const void* src) {
    asm volatile("cp.async.cg.shared.global [%0], [%1], 16;"
                 :: "r"(dst), "l"(src) : "memory");
}
#define CP_COMMIT() asm volatile("cp.async.commit_group;" ::: "memory")
#define CP_WAIT(n)  asm volatile("cp.async.wait_group %0;" :: "n"(n) : "memory")

// ---------------------------------------------------------------------------
// Setup: block k simulates basis state |k>; writes the 3 Karatsuba weights.
// ---------------------------------------------------------------------------
__global__ void build_weights_kernel(const float* __restrict__ params) {
    __shared__ float2 st[256];
    __shared__ float g[NLAYERS * NQ][8];
    int k = blockIdx.x;
    int t = threadIdx.x;

    if (t < NLAYERS * NQ) {
        const float* pr = params + t * 3;
        float hx = 0.5f * pr[0], hy = 0.5f * pr[1], hz = 0.5f * pr[2];
        float cx = cosf(hx), sx = sinf(hx);
        float cy = cosf(hy), sy = sinf(hy);
        float cz = cosf(hz), sz = sinf(hz);
        float m00r =  cy * cx, m00i =  sy * sx;
        float m01r = -sy * cx, m01i = -cy * sx;
        float m10r =  sy * cx, m10i = -cy * sx;
        float m11r =  cy * cx, m11i = -sy * sx;
        g[t][0] = cz * m00r + sz * m00i;  g[t][1] = cz * m00i - sz * m00r;
        g[t][2] = cz * m01r + sz * m01i;  g[t][3] = cz * m01i - sz * m01r;
        g[t][4] = cz * m10r - sz * m10i;  g[t][5] = cz * m10i + sz * m10r;
        g[t][6] = cz * m11r - sz * m11i;  g[t][7] = cz * m11i + sz * m11r;
    }
    st[t] = make_float2(t == k ? 1.0f : 0.0f, 0.0f);
    __syncthreads();

    for (int l = 0; l < NLAYERS; l++) {
        for (int q = 0; q < NQ; q++) {
            const float* u = g[l * NQ + q];
            float u00r = u[0], u00i = u[1], u01r = u[2], u01i = u[3];
            float u10r = u[4], u10i = u[5], u11r = u[6], u11i = u[7];
            int p = 7 - q;  // qubit 0 = MSB of flat index
            if (t < 128) {
                int lo = t & ((1 << p) - 1);
                int i0 = ((t >> p) << (p + 1)) | lo;
                int i1 = i0 | (1 << p);
                float2 a0 = st[i0], a1 = st[i1];
                float2 n0, n1;
                n0.x = u00r*a0.x - u00i*a0.y + u01r*a1.x - u01i*a1.y;
                n0.y = u00r*a0.y + u00i*a0.x + u01r*a1.y + u01i*a1.x;
                n1.x = u10r*a0.x - u10i*a0.y + u11r*a1.x - u11i*a1.y;
                n1.y = u10r*a0.y + u10i*a0.x + u11r*a1.y + u11i*a1.x;
                st[i0] = n0;
                st[i1] = n1;
            }
            __syncthreads();
        }
        for (int q = 0; q < NQ; q++) {
            int pc = 7 - q;
            int pt = 7 - ((q + 1) & 7);
            if (((t >> pc) & 1) == 1 && ((t >> pt) & 1) == 0) {
                int j = t | (1 << pt);
                float2 tmp = st[t];
                st[t] = st[j];
                st[j] = tmp;
            }
            __syncthreads();
        }
    }
    if (t < 128) {
        float re = st[t].x, im = st[t].y;
        Wg_global[0 * 32768 + t * 256 + k] = __float2half_rn(re);
        Wg_global[1 * 32768 + t * 256 + k] = __float2half_rn(im - re);
        Wg_global[2 * 32768 + t * 256 + k] = __float2half_rn(re + im);
    }
}

// ---------------------------------------------------------------------------
// GEMM: grid = 2048 m-tiles. CTA = 64 rows x 128 complex cols, 256 threads =
// 8 warps, warp grid 1(M) x 8(N), warp tile 64 x 16c x 3 planes.
// K = 256 in 4 chunks of 64.
// SMEM: A fp16 [stage(2) x op(2) x 8KB] = 32KB at 0 (op0=Sr, op1=Si);
//       B fp16 ring [stage(3) x op(3) x 16KB] = 144KB at 32KB.
//       red[64] aliases A in the epilogue.
// ---------------------------------------------------------------------------
static constexpr uint32_t OFF_B    = 32 * 1024;
static constexpr uint32_t B_STAGE  = 48 * 1024;   // 3 ops x 16KB
static constexpr uint32_t DYN_SMEM = 32 * 1024 + 3 * B_STAGE + 1024;

__global__ void __launch_bounds__(256, 1)
qmm_kernel(const float* __restrict__ sre, const float* __restrict__ sim,
           float* __restrict__ out) {
    extern __shared__ char smem_raw[];
    uint32_t base  = smem_u32(smem_raw);
    uint32_t abase = (base + 1023u) & ~1023u;
    char* a = smem_raw + (abase - base);
    float* red = (float*)a;   // aliases A region (dead by epilogue)

    const int tid  = threadIdx.x;
    const int wid  = tid >> 5;
    const int lane = tid & 31;
    const int wn   = wid;       // 0..7 : complex cols wn*16..+15

    // ldmatrix per-lane geometry
    const int r  = lane & 7;
    const int q  = lane >> 3;
    const uint32_t xorv = (uint32_t)r << 4;
    const uint32_t ch16 = (uint32_t)(q >> 1) << 4;
    const int rl = ((q & 1) << 3) + r;

    uint32_t aRow[4];
    #pragma unroll
    for (int mf = 0; mf < 4; mf++)
        aRow[mf] = abase + (uint32_t)(mf * 16 + rl) * 128;
    const uint32_t bRow = abase + OFF_B + (uint32_t)(wn * 16 + rl) * 128;

    const long tileBase = (long)blockIdx.x * 64;

    // acc[plane][mf][nf][i] : 96 regs
    float acc[3][4][2][4];
    #pragma unroll
    for (int p = 0; p < 3; p++)
        #pragma unroll
        for (int mf = 0; mf < 4; mf++)
            #pragma unroll
            for (int nf = 0; nf < 2; nf++)
                #pragma unroll
                for (int i = 0; i < 4; i++) acc[p][mf][nf][i] = 0.0f;

    // A: per chunk 64 rows x 16 float4 per source; 256 thr -> 4 + 4 (MLP 8)
    float4 av[8];

    auto ldgA = [&](int c) {
        int kb = c * 64;
        #pragma unroll
        for (int it = 0; it < 4; it++) {
            int i = tid + it * 256;
            int row = i >> 4, f4 = i & 15;
            av[it]     = *(const float4*)(sre + (tileBase + row) * 256 + kb + f4 * 4);
            av[4 + it] = *(const float4*)(sim + (tileBase + row) * 256 + kb + f4 * 4);
        }
    };
    auto stsA = [&](int c) {
        uint32_t stg = (uint32_t)(c & 1) * 16384u;
        #pragma unroll
        for (int it = 0; it < 4; it++) {
            int i = tid + it * 256;
            int row = i >> 4, f4 = i & 15;
            uint32_t byte = (uint32_t)row * 128 +
                            (((uint32_t)f4 * 8) ^ (((uint32_t)row & 7) << 4));
            __half2 r0 = __floats2half2_rn(av[it].x, av[it].y);
            __half2 r1 = __floats2half2_rn(av[it].z, av[it].w);
            __half2 i0 = __floats2half2_rn(av[4 + it].x, av[4 + it].y);
            __half2 i1 = __floats2half2_rn(av[4 + it].z, av[4 + it].w);
            uint2 v;
            v.x = *(const uint32_t*)&r0; v.y = *(const uint32_t*)&r1;
            *(uint2*)(a + stg + byte) = v;              // op0 = Sr
            v.x = *(const uint32_t*)&i0; v.y = *(const uint32_t*)&i1;
            *(uint2*)(a + stg + 8192 + byte) = v;       // op1 = Si
        }
    };
    // B chunk c -> ring stage c%3 (3 ops x 16KB); 3072 x 16B, 12 per thread
    auto issueB = [&](int c) {
        uint32_t sb = abase + OFF_B + (uint32_t)(c % 3) * B_STAGE;
        #pragma unroll
        for (int it = 0; it < 12; it++) {
            int i = tid + it * 256;
            int op = i >> 10;
            int j  = i & 1023;
            int n = j >> 3, seg = j & 7;
            uint32_t dst = sb + (uint32_t)op * 16384u + (uint32_t)n * 128 +
                           (((uint32_t)seg * 16) ^ (((uint32_t)n & 7) << 4));
            cp_async16(dst, Wg_global + op * 32768 + n * 256 + c * 64 + seg * 8);
        }
    };
    auto compute_ks = [&](int c, int ks) {
        uint32_t cx   = (((uint32_t)ks * 32) | ch16) ^ xorv;
        uint32_t astg = (uint32_t)(c & 1) * 16384u;
        uint32_t bstg = (uint32_t)(c % 3) * B_STAGE;
        uint32_t fr[4][4], fi[4][4], fs[4][4];
        #pragma unroll
        for (int mf = 0; mf < 4; mf++) {
            ldmatrix_x4(fr[mf], aRow[mf] + astg + cx);            // Sr
            ldmatrix_x4(fi[mf], aRow[mf] + astg + 8192u + cx);    // Si
            #pragma unroll
            for (int j = 0; j < 4; j++)
                fs[mf][j] = hadd2u(fr[mf][j], fi[mf][j]);         // Ssum
        }
        #pragma unroll
        for (int p = 0; p < 3; p++) {
            uint32_t bf[4];
            ldmatrix_x4(bf, bRow + bstg + (uint32_t)p * 16384u + cx);
            #pragma unroll
            for (int mf = 0; mf < 4; mf++) {
                const uint32_t* af = (p == 0) ? fs[mf] : (p == 1) ? fr[mf] : fi[mf];
                mma16816(acc[p][mf][0], af, bf[0], bf[2]);
                mma16816(acc[p][mf][1], af, bf[1], bf[3]);
            }
        }
    };

    // ---- prologue: B(0), B(1) in flight; A(0) converted into stage 0 ----
    issueB(0);
    CP_COMMIT();
    issueB(1);
    CP_COMMIT();
    ldgA(0);
    stsA(0);

    // ---- mainloop: 4 chunks of K=64, one sync per chunk ----
    for (int c = 0; c < 4; c++) {
        CP_WAIT(1);          // B(c) complete (B(c+1) may be in flight)
        __syncthreads();     // B(c) + A(c) visible; all warps past chunk c-1

        if (c < 2) issueB(c + 2);   // overwrites stage read in chunk c-1: safe
        CP_COMMIT();                // unconditional: uniform group count

        if (c < 3) ldgA(c + 1);
        compute_ks(c, 0);
        compute_ks(c, 1);
        if (c < 3) stsA(c + 1);
        compute_ks(c, 2);
        compute_ks(c, 3);
    }

    // ---- epilogue: Re = k1-k3, Im = k1+k2; out[m] = sum Re^2+Im^2 ----
    __syncthreads();
    if (tid < 64) red[tid] = 0.0f;
    __syncthreads();

    #pragma unroll
    for (int mf = 0; mf < 4; mf++) {
        float s_lo = 0.0f, s_hi = 0.0f;
        #pragma unroll
        for (int nf = 0; nf < 2; nf++) {
            #pragma unroll
            for (int i = 0; i < 4; i++) {
                float k1 = acc[0][mf][nf][i];
                float k2 = acc[1][mf][nf][i];
                float k3 = acc[2][mf][nf][i];
                float re = k1 - k3;
                float im = k1 + k2;
                float v = fmaf(re, re, im * im);
                if (i < 2) s_lo += v; else s_hi += v;
            }
        }
        s_lo += __shfl_xor_sync(0xFFFFFFFF, s_lo, 1);
        s_lo += __shfl_xor_sync(0xFFFFFFFF, s_lo, 2);
        s_hi += __shfl_xor_sync(0xFFFFFFFF, s_hi, 1);
        s_hi += __shfl_xor_sync(0xFFFFFFFF, s_hi, 2);
        if ((lane & 3) == 0) {
            int row = mf * 16 + (lane >> 2);
            atomicAdd(red + row, s_lo);
            atomicAdd(red + row + 8, s_hi);
        }
    }
    __syncthreads();
    if (tid < 64) out[tileBase + tid] = red[tid];
}

// ---------------------------------------------------------------------------
extern "C" void kernel_launch(void* const* d_in, const int* in_sizes, int n_in,
                              void* d_out, int out_size) {
    const float* params = (const float*)d_in[0];
    const float* sre    = (const float*)d_in[1];
    const float* sim    = (const float*)d_in[2];
    float* out = (float*)d_out;

    cudaFuncSetAttribute(qmm_kernel, cudaFuncAttributeMaxDynamicSharedMemorySize,
                         DYN_SMEM);

    build_weights_kernel<<<256, 256>>>(params);
    qmm_kernel<<<2048, 256, DYN_SMEM>>>(sre, sim, out);
}

// round 13
// speedup vs baseline: 1.2989x; 1.1368x over previous
#include <cuda_runtime.h>
#include <cuda_fp16.h>
#include <cstdint>

// ============================================================================
// out_i = || P * U(params) * s_i ||^2, 131072 states of dim 256.
// params batch-invariant -> precompute A = P*U (128x256 complex).
// Gauss/Karatsuba 3M complex GEMM, fp16 mma.sync, fp32 accumulation:
//   w = c+di, s = a+bi:  k1=(a+b)c, k2=a(d-c), k3=b(c+d)
//   Re = k1-k3, Im = k1+k2;  out_m = sum_n Re^2+Im^2
// Planes: p0: Ssum x c, p1: Sr x (d-c), p2: Si x (c+d); Ssum fragments
// derived from Sr/Si fragments via HADD2.
//
// R13: PERSISTENT CTAs. R12's 42us-over-floor decomposed to ~6.3K cycles of
//  per-CTA turnover (B prologue + CP_WAIT exposure + epilogue + launch/drain)
//  paid over 14 waves. Fix: grid = #SMs, each CTA loops over ~14 m-tiles;
//  B (192KB, all chunks+ops) resident, loaded ONCE per CTA; A prefetch flows
//  across tile boundaries; per-tile epilogue = register combine + global
//  atomicAdd (out zeroed in setup). Inner loop identical to R12's core.
// ============================================================================

#define NLAYERS 3
#define NQ 8
#define NTILES 2048

// Wg[op][n][k]: op0 = Ar, op1 = Ai - Ar, op2 = Ar + Ai.  (128 n x 256 k each)
__device__ __half Wg_global[3 * 128 * 256];

// ---------------------------------------------------------------------------
__device__ __forceinline__ uint32_t smem_u32(const void* p) {
    uint32_t a;
    asm("{ .reg .u64 t; cvta.to.shared.u64 t, %1; cvt.u32.u64 %0, t; }"
        : "=r"(a) : "l"(p));
    return a;
}

__device__ __forceinline__ void ldmatrix_x4(uint32_t r[4], uint32_t addr) {
    asm volatile("ldmatrix.sync.aligned.m8n8.x4.shared.b16 {%0,%1,%2,%3}, [%4];"
                 : "=r"(r[0]), "=r"(r[1]), "=r"(r[2]), "=r"(r[3]) : "r"(addr));
}

__device__ __forceinline__ void mma16816(float c[4], const uint32_t a[4],
                                         uint32_t b0, uint32_t b1) {
    asm volatile(
        "mma.sync.aligned.m16n8k16.row.col.f32.f16.f16.f32 "
        "{%0,%1,%2,%3}, {%4,%5,%6,%7}, {%8,%9}, {%0,%1,%2,%3};"
        : "+f"(c[0]), "+f"(c[1]), "+f"(c[2]), "+f"(c[3])
        : "r"(a[0]), "r"(a[1]), "r"(a[2]), "r"(a[3]), "r"(b0), "r"(b1));
}

__device__ __forceinline__ uint32_t hadd2u(uint32_t x, uint32_t y) {
    uint32_t z;
    asm("add.f16x2 %0, %1, %2;" : "=r"(z) : "r"(x), "r"(y));
    return z;
}

__device__ __forceinline__ void cp_async16(uint32_t dst, const void* src) {
    asm volatile("cp.async.cg.shared.global [%0], [%1], 16;"
                 :: "r"(dst), "l"(src) : "memory");
}
#define CP_COMMIT() asm volatile("cp.async.commit_group;" ::: "memory")
#define CP_WAIT0()  asm volatile("cp.async.wait_group 0;" ::: "memory")

// ---------------------------------------------------------------------------
// Setup: block k simulates basis state |k>; writes the 3 Karatsuba weights.
// Also zero-initializes d_out (poisoned by harness; qmm atomicAdds into it).
// ---------------------------------------------------------------------------
__global__ void build_weights_kernel(const float* __restrict__ params,
                                     float* __restrict__ out_zero) {
    __shared__ float2 st[256];
    __shared__ float g[NLAYERS * NQ][8];
    int k = blockIdx.x;
    int t = threadIdx.x;

    int zi = blockIdx.x * 256 + t;
    out_zero[zi] = 0.0f;
    out_zero[zi + 65536] = 0.0f;

    if (t < NLAYERS * NQ) {
        const float* pr = params + t * 3;
        float hx = 0.5f * pr[0], hy = 0.5f * pr[1], hz = 0.5f * pr[2];
        float cx = cosf(hx), sx = sinf(hx);
        float cy = cosf(hy), sy = sinf(hy);
        float cz = cosf(hz), sz = sinf(hz);
        float m00r =  cy * cx, m00i =  sy * sx;
        float m01r = -sy * cx, m01i = -cy * sx;
        float m10r =  sy * cx, m10i = -cy * sx;
        float m11r =  cy * cx, m11i = -sy * sx;
        g[t][0] = cz * m00r + sz * m00i;  g[t][1] = cz * m00i - sz * m00r;
        g[t][2] = cz * m01r + sz * m01i;  g[t][3] = cz * m01i - sz * m01r;
        g[t][4] = cz * m10r - sz * m10i;  g[t][5] = cz * m10i + sz * m10r;
        g[t][6] = cz * m11r - sz * m11i;  g[t][7] = cz * m11i + sz * m11r;
    }
    st[t] = make_float2(t == k ? 1.0f : 0.0f, 0.0f);
    __syncthreads();

    for (int l = 0; l < NLAYERS; l++) {
        for (int q = 0; q < NQ; q++) {
            const float* u = g[l * NQ + q];
            float u00r = u[0], u00i = u[1], u01r = u[2], u01i = u[3];
            float u10r = u[4], u10i = u[5], u11r = u[6], u11i = u[7];
            int p = 7 - q;  // qubit 0 = MSB of flat index
            if (t < 128) {
                int lo = t & ((1 << p) - 1);
                int i0 = ((t >> p) << (p + 1)) | lo;
                int i1 = i0 | (1 << p);
                float2 a0 = st[i0], a1 = st[i1];
                float2 n0, n1;
                n0.x = u00r*a0.x - u00i*a0.y + u01r*a1.x - u01i*a1.y;
                n0.y = u00r*a0.y + u00i*a0.x + u01r*a1.y + u01i*a1.x;
                n1.x = u10r*a0.x - u10i*a0.y + u11r*a1.x - u11i*a1.y;
                n1.y = u10r*a0.y + u10i*a0.x + u11r*a1.y + u11i*a1.x;
                st[i0] = n0;
                st[i1] = n1;
            }
            __syncthreads();
        }
        for (int q = 0; q < NQ; q++) {
            int pc = 7 - q;
            int pt = 7 - ((q + 1) & 7);
            if (((t >> pc) & 1) == 1 && ((t >> pt) & 1) == 0) {
                int j = t | (1 << pt);
                float2 tmp = st[t];
                st[t] = st[j];
                st[j] = tmp;
            }
            __syncthreads();
        }
    }
    if (t < 128) {
        float re = st[t].x, im = st[t].y;
        Wg_global[0 * 32768 + t * 256 + k] = __float2half_rn(re);
        Wg_global[1 * 32768 + t * 256 + k] = __float2half_rn(im - re);
        Wg_global[2 * 32768 + t * 256 + k] = __float2half_rn(re + im);
    }
}

// ---------------------------------------------------------------------------
// Persistent GEMM: grid = #SMs. Each CTA loops over m-tiles (64 rows each,
// tile-strided). CTA = 256 threads = 8 warps, warp grid 1(M) x 8(N),
// warp tile 64 x 16c x 3 planes (acc = 96 regs). K = 256 in 4 chunks of 64.
// SMEM: A fp16 [stage(2) x op(2) x 8KB] = 32KB at 0 (op0=Sr, op1=Si);
//       B fp16 RESIDENT [chunk(4) x op(3) x 16KB] = 192KB at 32KB,
//       loaded once per CTA lifetime.
// Output: per-tile register Gauss combine + quad shfl + global atomicAdd.
// ---------------------------------------------------------------------------
static constexpr uint32_t OFF_B    = 32 * 1024;
static constexpr uint32_t DYN_SMEM = 32 * 1024 + 192 * 1024 + 1024;  // 230400

__global__ void __launch_bounds__(256, 1)
qmm_kernel(const float* __restrict__ sre, const float* __restrict__ sim,
           float* __restrict__ out) {
    extern __shared__ char smem_raw[];
    uint32_t base  = smem_u32(smem_raw);
    uint32_t abase = (base + 1023u) & ~1023u;
    char* a = smem_raw + (abase - base);

    const int tid  = threadIdx.x;
    const int wid  = tid >> 5;
    const int lane = tid & 31;
    const int wn   = wid;       // 0..7 : complex cols wn*16..+15

    // ldmatrix per-lane geometry
    const int r  = lane & 7;
    const int q  = lane >> 3;
    const uint32_t xorv = (uint32_t)r << 4;
    const uint32_t ch16 = (uint32_t)(q >> 1) << 4;
    const int rl = ((q & 1) << 3) + r;

    uint32_t aRow[4];
    #pragma unroll
    for (int mf = 0; mf < 4; mf++)
        aRow[mf] = abase + (uint32_t)(mf * 16 + rl) * 128;
    const uint32_t bRow = abase + OFF_B + (uint32_t)(wn * 16 + rl) * 128;

    // ---- B resident load (once per CTA): 12288 x 16B, 256 thr -> 48 each --
    #pragma unroll
    for (int it = 0; it < 48; it++) {
        int i = tid + it * 256;
        int c  = i / 3072;
        int rm = i % 3072;
        int op = rm >> 10;
        int j  = rm & 1023;
        int n = j >> 3, seg = j & 7;
        uint32_t dst = abase + OFF_B + (uint32_t)(c * 3 + op) * 16384u +
                       (uint32_t)n * 128 +
                       (((uint32_t)seg * 16) ^ (((uint32_t)n & 7) << 4));
        cp_async16(dst, Wg_global + op * 32768 + n * 256 + c * 64 + seg * 8);
    }
    CP_COMMIT();

    // A: per chunk 64 rows x 16 float4 per source; 256 thr -> 4 + 4 (MLP 8)
    float4 av[8];
    auto ldgA = [&](long tb, int c) {
        int kb = c * 64;
        #pragma unroll
        for (int it = 0; it < 4; it++) {
            int i = tid + it * 256;
            int row = i >> 4, f4 = i & 15;
            av[it]     = *(const float4*)(sre + (tb + row) * 256 + kb + f4 * 4);
            av[4 + it] = *(const float4*)(sim + (tb + row) * 256 + kb + f4 * 4);
        }
    };
    auto stsA = [&](int stage) {
        uint32_t stg = (uint32_t)stage * 16384u;
        #pragma unroll
        for (int it = 0; it < 4; it++) {
            int i = tid + it * 256;
            int row = i >> 4, f4 = i & 15;
            uint32_t byte = (uint32_t)row * 128 +
                            (((uint32_t)f4 * 8) ^ (((uint32_t)row & 7) << 4));
            __half2 r0 = __floats2half2_rn(av[it].x, av[it].y);
            __half2 r1 = __floats2half2_rn(av[it].z, av[it].w);
            __half2 i0 = __floats2half2_rn(av[4 + it].x, av[4 + it].y);
            __half2 i1 = __floats2half2_rn(av[4 + it].z, av[4 + it].w);
            uint2 v;
            v.x = *(const uint32_t*)&r0; v.y = *(const uint32_t*)&r1;
            *(uint2*)(a + stg + byte) = v;              // op0 = Sr
            v.x = *(const uint32_t*)&i0; v.y = *(const uint32_t*)&i1;
            *(uint2*)(a + stg + 8192 + byte) = v;       // op1 = Si
        }
    };

    float acc[3][4][2][4];

    auto compute_ks = [&](int c, int ks) {
        uint32_t cx   = (((uint32_t)ks * 32) | ch16) ^ xorv;
        uint32_t astg = (uint32_t)(c & 1) * 16384u;
        uint32_t fr[4][4], fi[4][4], fs[4][4];
        #pragma unroll
        for (int mf = 0; mf < 4; mf++) {
            ldmatrix_x4(fr[mf], aRow[mf] + astg + cx);            // Sr
            ldmatrix_x4(fi[mf], aRow[mf] + astg + 8192u + cx);    // Si
            #pragma unroll
            for (int j = 0; j < 4; j++)
                fs[mf][j] = hadd2u(fr[mf][j], fi[mf][j]);         // Ssum
        }
        #pragma unroll
        for (int p = 0; p < 3; p++) {
            uint32_t bf[4];
            ldmatrix_x4(bf, bRow + (uint32_t)(c * 3 + p) * 16384u + cx);
            #pragma unroll
            for (int mf = 0; mf < 4; mf++) {
                const uint32_t* af = (p == 0) ? fs[mf] : (p == 1) ? fr[mf] : fi[mf];
                mma16816(acc[p][mf][0], af, bf[0], bf[2]);
                mma16816(acc[p][mf][1], af, bf[1], bf[3]);
            }
        }
    };

    // ---- prologue: A(tile0, chunk0) into stage 0; wait for resident B ----
    const int grid = gridDim.x;
    long tile0 = blockIdx.x;
    ldgA(tile0 * 64, 0);
    stsA(0);
    CP_WAIT0();

    // ---- persistent tile loop ----
    for (long ti = tile0; ti < NTILES; ti += grid) {
        const long tb = ti * 64;
        // next tile base, clamped to valid memory (results unused if invalid)
        long tnext = ti + grid;
        if (tnext >= NTILES) tnext = 0;
        const long tbn = tnext * 64;

        #pragma unroll
        for (int p = 0; p < 3; p++)
            #pragma unroll
            for (int mf = 0; mf < 4; mf++)
                #pragma unroll
                for (int nf = 0; nf < 2; nf++)
                    #pragma unroll
                    for (int i = 0; i < 4; i++) acc[p][mf][nf][i] = 0.0f;

        #pragma unroll
        for (int c = 0; c < 4; c++) {
            __syncthreads();   // A stage (c&1) + all warps past prior reads

            // prefetch A for next chunk (crosses tile boundary at c==3)
            ldgA((c < 3) ? tb : tbn, (c + 1) & 3);
            compute_ks(c, 0);
            compute_ks(c, 1);
            stsA((c & 1) ^ 1);
            compute_ks(c, 2);
            compute_ks(c, 3);
        }

        // ---- per-tile epilogue: Re=k1-k3, Im=k1+k2; atomicAdd to out ----
        #pragma unroll
        for (int mf = 0; mf < 4; mf++) {
            float s_lo = 0.0f, s_hi = 0.0f;
            #pragma unroll
            for (int nf = 0; nf < 2; nf++) {
                #pragma unroll
                for (int i = 0; i < 4; i++) {
                    float k1 = acc[0][mf][nf][i];
                    float k2 = acc[1][mf][nf][i];
                    float k3 = acc[2][mf][nf][i];
                    float re = k1 - k3;
                    float im = k1 + k2;
                    float v = fmaf(re, re, im * im);
                    if (i < 2) s_lo += v; else s_hi += v;
                }
            }
            s_lo += __shfl_xor_sync(0xFFFFFFFF, s_lo, 1);
            s_lo += __shfl_xor_sync(0xFFFFFFFF, s_lo, 2);
            s_hi += __shfl_xor_sync(0xFFFFFFFF, s_hi, 1);
            s_hi += __shfl_xor_sync(0xFFFFFFFF, s_hi, 2);
            if ((lane & 3) == 0) {
                long row = tb + mf * 16 + (lane >> 2);
                atomicAdd(out + row, s_lo);
                atomicAdd(out + row + 8, s_hi);
            }
        }
    }
}

// ---------------------------------------------------------------------------
extern "C" void kernel_launch(void* const* d_in, const int* in_sizes, int n_in,
                              void* d_out, int out_size) {
    const float* params = (const float*)d_in[0];
    const float* sre    = (const float*)d_in[1];
    const float* sim    = (const float*)d_in[2];
    float* out = (float*)d_out;

    cudaFuncSetAttribute(qmm_kernel, cudaFuncAttributeMaxDynamicSharedMemorySize,
                         DYN_SMEM);

    int nsm = 148;
    cudaDeviceGetAttribute(&nsm, cudaDevAttrMultiProcessorCount, 0);
    if (nsm < 1) nsm = 148;

    build_weights_kernel<<<256, 256>>>(params, out);
    qmm_kernel<<<nsm, 256, DYN_SMEM>>>(sre, sim, out);
}

// round 14
// speedup vs baseline: 1.3728x; 1.0569x over previous
#include <cuda_runtime.h>
#include <cuda_fp16.h>
#include <cstdint>

// ============================================================================
// out_i = || P * U(params) * s_i ||^2, 131072 states of dim 256.
// params batch-invariant -> precompute A = P*U (128x256 complex).
// Gauss/Karatsuba 3M complex GEMM, fp16 mma.sync, fp32 accumulation:
//   w = c+di, s = a+bi:  k1=(a+b)c, k2=a(d-c), k3=b(c+d)
//   Re = k1-k3, Im = k1+k2;  out_m = sum_n Re^2+Im^2
// Planes: p0: Ssum x c, p1: Sr x (d-c), p2: Si x (c+d); Ssum via HADD2.
//
// R14: de-bubble R13's inner loop (tensor was 38.3% vs the 50% fp32-acc cap;
//  R6 proved 50%+ is reachable). Three changes:
//   1. warp grid 2M x 4N (tile 32x32c): A LDSM 8->4, HADD2 16->8 per ks.
//   2. plane order p1,p2,p0: the HADD2-dependent Ssum plane issues last,
//      hidden under 16 independent MMAs.
//   3. ks order staggered by warp parity: SMSP warp pairs leave each sync
//      out of phase, keeping the tensor unit fed.
//  Persistent skeleton unchanged: grid=#SMs, B (192KB) resident per CTA,
//  A double-buffer flowing across tile boundaries, atomicAdd epilogue.
// ============================================================================

#define NLAYERS 3
#define NQ 8
#define NTILES 2048

// Wg[op][n][k]: op0 = Ar, op1 = Ai - Ar, op2 = Ar + Ai.  (128 n x 256 k each)
__device__ __half Wg_global[3 * 128 * 256];

// ---------------------------------------------------------------------------
__device__ __forceinline__ uint32_t smem_u32(const void* p) {
    uint32_t a;
    asm("{ .reg .u64 t; cvta.to.shared.u64 t, %1; cvt.u32.u64 %0, t; }"
        : "=r"(a) : "l"(p));
    return a;
}

__device__ __forceinline__ void ldmatrix_x4(uint32_t r[4], uint32_t addr) {
    asm volatile("ldmatrix.sync.aligned.m8n8.x4.shared.b16 {%0,%1,%2,%3}, [%4];"
                 : "=r"(r[0]), "=r"(r[1]), "=r"(r[2]), "=r"(r[3]) : "r"(addr));
}

__device__ __forceinline__ void mma16816(float c[4], const uint32_t a[4],
                                         uint32_t b0, uint32_t b1) {
    asm volatile(
        "mma.sync.aligned.m16n8k16.row.col.f32.f16.f16.f32 "
        "{%0,%1,%2,%3}, {%4,%5,%6,%7}, {%8,%9}, {%0,%1,%2,%3};"
        : "+f"(c[0]), "+f"(c[1]), "+f"(c[2]), "+f"(c[3])
        : "r"(a[0]), "r"(a[1]), "r"(a[2]), "r"(a[3]), "r"(b0), "r"(b1));
}

__device__ __forceinline__ uint32_t hadd2u(uint32_t x, uint32_t y) {
    uint32_t z;
    asm("add.f16x2 %0, %1, %2;" : "=r"(z) : "r"(x), "r"(y));
    return z;
}

__device__ __forceinline__ void cp_async16(uint32_t dst, const void* src) {
    asm volatile("cp.async.cg.shared.global [%0], [%1], 16;"
                 :: "r"(dst), "l"(src) : "memory");
}
#define CP_COMMIT() asm volatile("cp.async.commit_group;" ::: "memory")
#define CP_WAIT0()  asm volatile("cp.async.wait_group 0;" ::: "memory")

// ---------------------------------------------------------------------------
// Setup: block k simulates basis state |k>; writes the 3 Karatsuba weights.
// Also zero-initializes d_out (poisoned by harness; qmm atomicAdds into it).
// ---------------------------------------------------------------------------
__global__ void build_weights_kernel(const float* __restrict__ params,
                                     float* __restrict__ out_zero) {
    __shared__ float2 st[256];
    __shared__ float g[NLAYERS * NQ][8];
    int k = blockIdx.x;
    int t = threadIdx.x;

    int zi = blockIdx.x * 256 + t;
    out_zero[zi] = 0.0f;
    out_zero[zi + 65536] = 0.0f;

    if (t < NLAYERS * NQ) {
        const float* pr = params + t * 3;
        float hx = 0.5f * pr[0], hy = 0.5f * pr[1], hz = 0.5f * pr[2];
        float cx = cosf(hx), sx = sinf(hx);
        float cy = cosf(hy), sy = sinf(hy);
        float cz = cosf(hz), sz = sinf(hz);
        float m00r =  cy * cx, m00i =  sy * sx;
        float m01r = -sy * cx, m01i = -cy * sx;
        float m10r =  sy * cx, m10i = -cy * sx;
        float m11r =  cy * cx, m11i = -sy * sx;
        g[t][0] = cz * m00r + sz * m00i;  g[t][1] = cz * m00i - sz * m00r;
        g[t][2] = cz * m01r + sz * m01i;  g[t][3] = cz * m01i - sz * m01r;
        g[t][4] = cz * m10r - sz * m10i;  g[t][5] = cz * m10i + sz * m10r;
        g[t][6] = cz * m11r - sz * m11i;  g[t][7] = cz * m11i + sz * m11r;
    }
    st[t] = make_float2(t == k ? 1.0f : 0.0f, 0.0f);
    __syncthreads();

    for (int l = 0; l < NLAYERS; l++) {
        for (int q = 0; q < NQ; q++) {
            const float* u = g[l * NQ + q];
            float u00r = u[0], u00i = u[1], u01r = u[2], u01i = u[3];
            float u10r = u[4], u10i = u[5], u11r = u[6], u11i = u[7];
            int p = 7 - q;  // qubit 0 = MSB of flat index
            if (t < 128) {
                int lo = t & ((1 << p) - 1);
                int i0 = ((t >> p) << (p + 1)) | lo;
                int i1 = i0 | (1 << p);
                float2 a0 = st[i0], a1 = st[i1];
                float2 n0, n1;
                n0.x = u00r*a0.x - u00i*a0.y + u01r*a1.x - u01i*a1.y;
                n0.y = u00r*a0.y + u00i*a0.x + u01r*a1.y + u01i*a1.x;
                n1.x = u10r*a0.x - u10i*a0.y + u11r*a1.x - u11i*a1.y;
                n1.y = u10r*a0.y + u10i*a0.x + u11r*a1.y + u11i*a1.x;
                st[i0] = n0;
                st[i1] = n1;
            }
            __syncthreads();
        }
        for (int q = 0; q < NQ; q++) {
            int pc = 7 - q;
            int pt = 7 - ((q + 1) & 7);
            if (((t >> pc) & 1) == 1 && ((t >> pt) & 1) == 0) {
                int j = t | (1 << pt);
                float2 tmp = st[t];
                st[t] = st[j];
                st[j] = tmp;
            }
            __syncthreads();
        }
    }
    if (t < 128) {
        float re = st[t].x, im = st[t].y;
        Wg_global[0 * 32768 + t * 256 + k] = __float2half_rn(re);
        Wg_global[1 * 32768 + t * 256 + k] = __float2half_rn(im - re);
        Wg_global[2 * 32768 + t * 256 + k] = __float2half_rn(re + im);
    }
}

// ---------------------------------------------------------------------------
// Persistent GEMM: grid = #SMs. Each CTA loops over m-tiles (64 rows each).
// CTA = 256 threads = 8 warps, warp grid 2(M) x 4(N), warp tile 32 x 32c x
// 3 planes (acc = 96 regs). K = 256 in 4 chunks of 64.
// SMEM: A fp16 [stage(2) x op(2) x 8KB] = 32KB at 0 (op0=Sr, op1=Si);
//       B fp16 RESIDENT [chunk(4) x op(3) x 16KB] = 192KB at 32KB.
// Output: per-tile register Gauss combine + quad shfl + global atomicAdd.
// ---------------------------------------------------------------------------
static constexpr uint32_t OFF_B    = 32 * 1024;
static constexpr uint32_t DYN_SMEM = 32 * 1024 + 192 * 1024 + 1024;  // 230400

__global__ void __launch_bounds__(256, 1)
qmm_kernel(const float* __restrict__ sre, const float* __restrict__ sim,
           float* __restrict__ out) {
    extern __shared__ char smem_raw[];
    uint32_t base  = smem_u32(smem_raw);
    uint32_t abase = (base + 1023u) & ~1023u;
    char* a = smem_raw + (abase - base);

    const int tid  = threadIdx.x;
    const int wid  = tid >> 5;
    const int lane = tid & 31;
    const int wm   = wid >> 2;          // 0..1 : rows wm*32..+31
    const int wn   = wid & 3;           // 0..3 : complex cols wn*32..+31
    const int kst  = (wid & 1) << 1;    // ks stagger: even warps 0, odd 2

    // ldmatrix per-lane geometry
    const int r  = lane & 7;
    const int q  = lane >> 3;
    const uint32_t xorv = (uint32_t)r << 4;
    const uint32_t ch16 = (uint32_t)(q >> 1) << 4;
    const int rl = ((q & 1) << 3) + r;

    uint32_t aRow[2], bRow[2];
    #pragma unroll
    for (int mf = 0; mf < 2; mf++)
        aRow[mf] = abase + (uint32_t)(wm * 32 + mf * 16 + rl) * 128;
    #pragma unroll
    for (int nb = 0; nb < 2; nb++)
        bRow[nb] = abase + OFF_B + (uint32_t)(wn * 32 + nb * 16 + rl) * 128;

    // ---- B resident load (once per CTA): 12288 x 16B, 256 thr -> 48 each --
    #pragma unroll
    for (int it = 0; it < 48; it++) {
        int i = tid + it * 256;
        int c  = i / 3072;
        int rm = i % 3072;
        int op = rm >> 10;
        int j  = rm & 1023;
        int n = j >> 3, seg = j & 7;
        uint32_t dst = abase + OFF_B + (uint32_t)(c * 3 + op) * 16384u +
                       (uint32_t)n * 128 +
                       (((uint32_t)seg * 16) ^ (((uint32_t)n & 7) << 4));
        cp_async16(dst, Wg_global + op * 32768 + n * 256 + c * 64 + seg * 8);
    }
    CP_COMMIT();

    // A: per chunk 64 rows x 16 float4 per source; 256 thr -> 4 + 4 (MLP 8)
    float4 av[8];
    auto ldgA = [&](long tb, int c) {
        int kb = c * 64;
        #pragma unroll
        for (int it = 0; it < 4; it++) {
            int i = tid + it * 256;
            int row = i >> 4, f4 = i & 15;
            av[it]     = *(const float4*)(sre + (tb + row) * 256 + kb + f4 * 4);
            av[4 + it] = *(const float4*)(sim + (tb + row) * 256 + kb + f4 * 4);
        }
    };
    auto stsA = [&](int stage) {
        uint32_t stg = (uint32_t)stage * 16384u;
        #pragma unroll
        for (int it = 0; it < 4; it++) {
            int i = tid + it * 256;
            int row = i >> 4, f4 = i & 15;
            uint32_t byte = (uint32_t)row * 128 +
                            (((uint32_t)f4 * 8) ^ (((uint32_t)row & 7) << 4));
            __half2 r0 = __floats2half2_rn(av[it].x, av[it].y);
            __half2 r1 = __floats2half2_rn(av[it].z, av[it].w);
            __half2 i0 = __floats2half2_rn(av[4 + it].x, av[4 + it].y);
            __half2 i1 = __floats2half2_rn(av[4 + it].z, av[4 + it].w);
            uint2 v;
            v.x = *(const uint32_t*)&r0; v.y = *(const uint32_t*)&r1;
            *(uint2*)(a + stg + byte) = v;              // op0 = Sr
            v.x = *(const uint32_t*)&i0; v.y = *(const uint32_t*)&i1;
            *(uint2*)(a + stg + 8192 + byte) = v;       // op1 = Si
        }
    };

    float acc[3][2][4][4];

    // Plane order p1 (fr), p2 (fi), p0 (fs = HADD2(fr,fi)) — the dependent
    // Ssum plane issues last, hidden behind 16 independent MMAs.
    auto compute_ks = [&](int c, int ks) {
        uint32_t cx   = (((uint32_t)ks * 32) | ch16) ^ xorv;
        uint32_t astg = (uint32_t)(c & 1) * 16384u;
        uint32_t bstg = (uint32_t)(c * 3) * 16384u;
        uint32_t fr[2][4], fi[2][4], fs[2][4];
        #pragma unroll
        for (int mf = 0; mf < 2; mf++)
            ldmatrix_x4(fr[mf], aRow[mf] + astg + cx);            // Sr
        #pragma unroll
        for (int mf = 0; mf < 2; mf++)
            ldmatrix_x4(fi[mf], aRow[mf] + astg + 8192u + cx);    // Si

        // p1: Sr x (d-c)
        {
            uint32_t bf[2][4];
            #pragma unroll
            for (int nb = 0; nb < 2; nb++)
                ldmatrix_x4(bf[nb], bRow[nb] + bstg + 16384u + cx);
            #pragma unroll
            for (int mf = 0; mf < 2; mf++)
                #pragma unroll
                for (int nf = 0; nf < 4; nf++) {
                    int nb = nf >> 1, sub = nf & 1;
                    mma16816(acc[1][mf][nf], fr[mf], bf[nb][sub], bf[nb][sub + 2]);
                }
        }
        // p2: Si x (c+d)
        {
            uint32_t bf[2][4];
            #pragma unroll
            for (int nb = 0; nb < 2; nb++)
                ldmatrix_x4(bf[nb], bRow[nb] + bstg + 32768u + cx);
            #pragma unroll
            for (int mf = 0; mf < 2; mf++)
                #pragma unroll
                for (int nf = 0; nf < 4; nf++) {
                    int nb = nf >> 1, sub = nf & 1;
                    mma16816(acc[2][mf][nf], fi[mf], bf[nb][sub], bf[nb][sub + 2]);
                }
        }
        // p0: Ssum x c
        #pragma unroll
        for (int mf = 0; mf < 2; mf++)
            #pragma unroll
            for (int j = 0; j < 4; j++)
                fs[mf][j] = hadd2u(fr[mf][j], fi[mf][j]);
        {
            uint32_t bf[2][4];
            #pragma unroll
            for (int nb = 0; nb < 2; nb++)
                ldmatrix_x4(bf[nb], bRow[nb] + bstg + cx);
            #pragma unroll
            for (int mf = 0; mf < 2; mf++)
                #pragma unroll
                for (int nf = 0; nf < 4; nf++) {
                    int nb = nf >> 1, sub = nf & 1;
                    mma16816(acc[0][mf][nf], fs[mf], bf[nb][sub], bf[nb][sub + 2]);
                }
        }
    };

    // ---- prologue: A(tile0, chunk0) into stage 0; wait for resident B ----
    const int grid = gridDim.x;
    long tile0 = blockIdx.x;
    ldgA(tile0 * 64, 0);
    stsA(0);
    CP_WAIT0();

    // ---- persistent tile loop ----
    for (long ti = tile0; ti < NTILES; ti += grid) {
        const long tb = ti * 64;
        long tnext = ti + grid;
        if (tnext >= NTILES) tnext = 0;   // clamped; results unused
        const long tbn = tnext * 64;

        #pragma unroll
        for (int p = 0; p < 3; p++)
            #pragma unroll
            for (int mf = 0; mf < 2; mf++)
                #pragma unroll
                for (int nf = 0; nf < 4; nf++)
                    #pragma unroll
                    for (int i = 0; i < 4; i++) acc[p][mf][nf][i] = 0.0f;

        #pragma unroll
        for (int c = 0; c < 4; c++) {
            __syncthreads();   // A stage (c&1) visible; all warps past prior reads

            ldgA((c < 3) ? tb : tbn, (c + 1) & 3);
            compute_ks(c, kst ^ 0);
            compute_ks(c, kst ^ 1);
            stsA((c & 1) ^ 1);
            compute_ks(c, kst ^ 2);
            compute_ks(c, kst ^ 3);
        }

        // ---- per-tile epilogue: Re=k1-k3, Im=k1+k2; atomicAdd to out ----
        #pragma unroll
        for (int mf = 0; mf < 2; mf++) {
            float s_lo = 0.0f, s_hi = 0.0f;
            #pragma unroll
            for (int nf = 0; nf < 4; nf++) {
                #pragma unroll
                for (int i = 0; i < 4; i++) {
                    float k1 = acc[0][mf][nf][i];
                    float k2 = acc[1][mf][nf][i];
                    float k3 = acc[2][mf][nf][i];
                    float re = k1 - k3;
                    float im = k1 + k2;
                    float v = fmaf(re, re, im * im);
                    if (i < 2) s_lo += v; else s_hi += v;
                }
            }
            s_lo += __shfl_xor_sync(0xFFFFFFFF, s_lo, 1);
            s_lo += __shfl_xor_sync(0xFFFFFFFF, s_lo, 2);
            s_hi += __shfl_xor_sync(0xFFFFFFFF, s_hi, 1);
            s_hi += __shfl_xor_sync(0xFFFFFFFF, s_hi, 2);
            if ((lane & 3) == 0) {
                long row = tb + wm * 32 + mf * 16 + (lane >> 2);
                atomicAdd(out + row, s_lo);
                atomicAdd(out + row + 8, s_hi);
            }
        }
    }
}

// ---------------------------------------------------------------------------
extern "C" void kernel_launch(void* const* d_in, const int* in_sizes, int n_in,
                              void* d_out, int out_size) {
    const float* params = (const float*)d_in[0];
    const float* sre    = (const float*)d_in[1];
    const float* sim    = (const float*)d_in[2];
    float* out = (float*)d_out;

    cudaFuncSetAttribute(qmm_kernel, cudaFuncAttributeMaxDynamicSharedMemorySize,
                         DYN_SMEM);

    int nsm = 148;
    cudaDeviceGetAttribute(&nsm, cudaDevAttrMultiProcessorCount, 0);
    if (nsm < 1) nsm = 148;

    build_weights_kernel<<<256, 256>>>(params, out);
    qmm_kernel<<<nsm, 256, DYN_SMEM>>>(sre, sim, out);
}